// round 17
// baseline (speedup 1.0000x reference)
#include <cuda_runtime.h>
#include <cuda_fp16.h>
#include <cstdint>

// Shapes fixed: B=16, N=64, D=E=256. Output: [new_nodes 1024x256 | h 65536x256] f32.
#define NROWS     1024
#define OUT_H_OFF (NROWS * 256)

// ---------------- device scratch ----------------
__device__ float    g_PQ[NROWS * 512];    // P = nodes@W1 + b_in | Q = nodes@W2
__device__ uint32_t g_W3p[128 * 256];     // W3 fp16 k-pair packed: [kp][n]
__device__ float    g_res[NROWS * 256];   // attn-weighted residual

// ---------------- helpers ----------------
__device__ __forceinline__ uint32_t pack2h(float lo, float hi) {
    __half2 h = __floats2half2_rn(lo, hi);
    return *(uint32_t*)&h;
}
__device__ __forceinline__ void mma_f16(float* c, const uint32_t* a, const uint32_t* b) {
    asm volatile(
        "mma.sync.aligned.m16n8k16.row.col.f32.f16.f16.f32 "
        "{%0,%1,%2,%3}, {%4,%5,%6,%7}, {%8,%9}, {%0,%1,%2,%3};"
        : "+f"(c[0]), "+f"(c[1]), "+f"(c[2]), "+f"(c[3])
        : "r"(a[0]), "r"(a[1]), "r"(a[2]), "r"(a[3]), "r"(b[0]), "r"(b[1]));
}
__device__ __forceinline__ uint32_t smem_u32(const void* p) {
    uint32_t a;
    asm("{ .reg .u64 t; cvta.to.shared.u64 t, %1; cvt.u32.u64 %0, t; }" : "=r"(a) : "l"(p));
    return a;
}
#define CP_ASYNC16(dst, src) \
    asm volatile("cp.async.cg.shared.global [%0], [%1], 16;" :: "r"(dst), "l"(src))
#define CP_COMMIT()  asm volatile("cp.async.commit_group;" ::: "memory")
#define CP_WAIT1()   asm volatile("cp.async.wait_group 1;" ::: "memory")
#define CP_WAIT0()   asm volatile("cp.async.wait_group 0;" ::: "memory")

// ---------------- smem layout for gnn_main10 (bytes) ----------------
// K-chunk = 64: E tile fp16 [64 rows][72 halves] (stride 144B) = 9216
// W bufs [32 kp][264] u32 = 33792 each
#define ESM_OFF   0        // 9216
#define WC0_OFF   9216     // -> 43008
#define WC1_OFF   43008    // -> 76800
#define HS_OFF    0        // epilogue overlay [64][260] f = 66560 (< 76800)
#define PS_OFF    76800    // 256 f
#define WCS_OFF   77824    // 256 f
#define CP_OFF    78848    // [4][64] f
#define COEF_OFF  79872    // 64 f
#define ATTN_OFF  80128    // 64 f
#define SMEM_BYTES 80384

// ===========================================================================
// Kernel A: blocks 0..127 -> PQ via fp16 mma (R16-exact);
// blocks 128..159 -> W3 fp16 k-pair pack. grid 160 x 256.
// ===========================================================================
__global__ __launch_bounds__(256) void prep9(
    const float* __restrict__ nodes, const float* __restrict__ W_in, const float* __restrict__ b_in)
{
    __shared__ uint32_t Asm[64 * 20];
    __shared__ uint32_t Wsm[16 * 72];

    const int tid = threadIdx.x;

    if (blockIdx.x >= 128) {
        const float* W3 = W_in + (size_t)512 * 256;
#pragma unroll
        for (int u = 0; u < 4; ++u) {
            int o = (blockIdx.x - 128) * 1024 + u * 256 + tid;
            int kp = o >> 8, n = o & 255;
            g_W3p[o] = pack2h(W3[(size_t)(2 * kp) * 256 + n],
                              W3[(size_t)(2 * kp + 1) * 256 + n]);
        }
        return;
    }

    const int cb = blockIdx.x & 7;
    const int rb = blockIdx.x >> 3;
    const int wrow = (cb >= 4) ? 256 : 0;
    const int nbase = (cb & 3) * 64;
    const int wid = tid >> 5;
    const int l   = tid & 31;
    const int mw  = wid >> 1;
    const int nw  = wid & 1;
    const int rg  = l >> 2;
    const int tg  = l & 3;

    const int er = tid >> 2;
    const int ek = (tid & 3) * 8;
    float4 apf0, apf1;
    auto loadA = [&](int ch) {
        const float* p = nodes + (size_t)(rb * 64 + er) * 256 + ch * 32 + ek;
        apf0 = *(const float4*)p;
        apf1 = *(const float4*)(p + 4);
    };
    auto stsA = [&]() {
        uint4 u;
        u.x = pack2h(apf0.x, apf0.y);
        u.y = pack2h(apf0.z, apf0.w);
        u.z = pack2h(apf1.x, apf1.y);
        u.w = pack2h(apf1.z, apf1.w);
        *(uint4*)((char*)Asm + er * 80 + ek * 2) = u;
    };

    float wlo[4], whi[4];
    auto loadW = [&](int ch) {
#pragma unroll
        for (int u = 0; u < 4; ++u) {
            int idx = tid + u * 256;
            int kp = idx >> 6, n = idx & 63;
            int row = wrow + ch * 32 + 2 * kp;
            wlo[u] = W_in[(size_t)row * 256 + nbase + n];
            whi[u] = W_in[(size_t)(row + 1) * 256 + nbase + n];
        }
    };
    auto stsW = [&]() {
#pragma unroll
        for (int u = 0; u < 4; ++u) {
            int idx = tid + u * 256;
            int kp = idx >> 6, n = idx & 63;
            Wsm[kp * 72 + n] = pack2h(wlo[u], whi[u]);
        }
    };

    float acc[4][4];
#pragma unroll
    for (int nt = 0; nt < 4; ++nt)
#pragma unroll
        for (int q = 0; q < 4; ++q) acc[nt][q] = 0.f;

    loadA(0);
    loadW(0);

    for (int ch = 0; ch < 8; ++ch) {
        stsA();
        stsW();
        __syncthreads();

        if (ch < 7) { loadA(ch + 1); loadW(ch + 1); }

#pragma unroll
        for (int s = 0; s < 2; ++s) {
            const int kh = s * 8;
            uint32_t a[4], b[4][2];
            int r0 = mw * 16 + rg;
            a[0] = Asm[r0 * 20 + kh + tg];
            a[1] = Asm[(r0 + 8) * 20 + kh + tg];
            a[2] = Asm[r0 * 20 + kh + tg + 4];
            a[3] = Asm[(r0 + 8) * 20 + kh + tg + 4];
            const uint32_t* Wk0 = Wsm + (kh + tg) * 72;
            const uint32_t* Wk1 = Wsm + (kh + tg + 4) * 72;
#pragma unroll
            for (int nt = 0; nt < 4; ++nt) {
                int n0 = nw * 32 + nt * 8 + rg;
                b[nt][0] = Wk0[n0];
                b[nt][1] = Wk1[n0];
            }
#pragma unroll
            for (int nt = 0; nt < 4; ++nt)
                mma_f16(acc[nt], a, b[nt]);
        }
        __syncthreads();
    }

    const int rA = rb * 64 + mw * 16 + rg;
    const int rB = rA + 8;
#pragma unroll
    for (int nt = 0; nt < 4; ++nt) {
        int c = cb * 64 + nw * 32 + nt * 8 + tg * 2;
        float bx = 0.f, by = 0.f;
        if (cb < 4) { float2 bv = *(const float2*)(b_in + c); bx = bv.x; by = bv.y; }
        *(float2*)(g_PQ + (size_t)rA * 512 + c) = make_float2(acc[nt][0] + bx, acc[nt][1] + by);
        *(float2*)(g_PQ + (size_t)rB * 512 + c) = make_float2(acc[nt][2] + bx, acc[nt][3] + by);
    }
}

// ===========================================================================
// Kernel B: fp16 mma + fused attention, K-chunk 64 (4 pipeline rounds, 8
// barriers vs 16). Fragment mapping identical to R13/R16 (proven numerics).
// ===========================================================================
__global__ __launch_bounds__(256) void gnn_main10(
    const float* __restrict__ edges,
    const float* __restrict__ W_coef,
    float* __restrict__ out)
{
    extern __shared__ char sm[];
    const uint32_t sbase = smem_u32(sm);
    float* hs   = (float*)(sm + HS_OFF);
    float* ps   = (float*)(sm + PS_OFF);
    float* wcs  = (float*)(sm + WCS_OFF);
    float* cp   = (float*)(sm + CP_OFF);
    float* coef_s = (float*)(sm + COEF_OFF);
    float* attn_s = (float*)(sm + ATTN_OFF);

    const int tid = threadIdx.x;
    const int wid = tid >> 5;
    const int l   = tid & 31;
    const int mw  = wid >> 2;
    const int nw  = wid & 3;
    const int rg  = l >> 2;
    const int tg  = l & 3;
    const int bid = blockIdx.x;
    const int b64 = (bid >> 6) << 6;
    const int i_g = bid & 63;

    ps[tid]  = g_PQ[(size_t)bid * 512 + tid];
    wcs[tid] = W_coef[tid];

    const float* Ebase = edges + (size_t)bid * 64 * 256;

    // ---- E staging: 64 rows x 64 k per chunk; per thread 2x(2 float4) ----
    const int er = tid >> 2;              // row 0..63
    const int ek = (tid & 3) * 16;        // halves offset 0,16,32,48
    float4 epf[4];
    auto loadE = [&](int ch) {
        const float* p = Ebase + (size_t)er * 256 + ch * 64 + ek;
        epf[0] = *(const float4*)p;
        epf[1] = *(const float4*)(p + 4);
        epf[2] = *(const float4*)(p + 8);
        epf[3] = *(const float4*)(p + 12);
    };
    auto stsE = [&]() {
        uint4 u0, u1;
        u0.x = pack2h(epf[0].x, epf[0].y);
        u0.y = pack2h(epf[0].z, epf[0].w);
        u0.z = pack2h(epf[1].x, epf[1].y);
        u0.w = pack2h(epf[1].z, epf[1].w);
        u1.x = pack2h(epf[2].x, epf[2].y);
        u1.y = pack2h(epf[2].z, epf[2].w);
        u1.z = pack2h(epf[3].x, epf[3].y);
        u1.w = pack2h(epf[3].z, epf[3].w);
        char* dst = sm + ESM_OFF + er * 144 + ek * 2;
        *(uint4*)dst = u0;
        *(uint4*)(dst + 16) = u1;
    };

    // ---- W staging: 32 kp x 256 n per chunk, cp.async ----
    auto stageW = [&](int ch, int buf) {
        uint32_t w_dst = sbase + (buf ? WC1_OFF : WC0_OFF);
#pragma unroll
        for (int u = 0; u < 8; ++u) {
            int idx = tid + u * 256;              // 0..2047
            int kp = idx >> 6, n4 = (idx & 63) << 2;
            CP_ASYNC16(w_dst + (uint32_t)(kp * 264 + n4) * 4,
                       g_W3p + (size_t)(ch * 32 + kp) * 256 + n4);
        }
    };

    float acc[2][8][4];
#pragma unroll
    for (int mt = 0; mt < 2; ++mt)
#pragma unroll
        for (int nt = 0; nt < 8; ++nt)
#pragma unroll
            for (int q = 0; q < 4; ++q) acc[mt][nt][q] = 0.f;

    loadE(0);
    stageW(0, 0);
    CP_COMMIT();

    for (int ch = 0; ch < 4; ++ch) {
        stsE();
        if (ch < 3) {
            stageW(ch + 1, (ch + 1) & 1);
            CP_COMMIT();
            CP_WAIT1();
        } else {
            CP_WAIT0();
        }
        __syncthreads();

        if (ch < 3) loadE(ch + 1);

        const uint32_t* EchU = (const uint32_t*)(sm + ESM_OFF);
        const uint32_t* WchU = (const uint32_t*)(sm + ((ch & 1) ? WC1_OFF : WC0_OFF));

#pragma unroll
        for (int s = 0; s < 4; ++s) {             // four k16 steps per 64-chunk
            const int kh = s * 8;
            uint32_t a[2][4], b[8][2];
#pragma unroll
            for (int mt = 0; mt < 2; ++mt) {
                int r0 = mw * 32 + mt * 16 + rg;
                a[mt][0] = EchU[r0 * 36 + kh + tg];
                a[mt][1] = EchU[(r0 + 8) * 36 + kh + tg];
                a[mt][2] = EchU[r0 * 36 + kh + tg + 4];
                a[mt][3] = EchU[(r0 + 8) * 36 + kh + tg + 4];
            }
            const uint32_t* Wk0 = WchU + (kh + tg) * 264;
            const uint32_t* Wk1 = WchU + (kh + tg + 4) * 264;
#pragma unroll
            for (int nt = 0; nt < 8; ++nt) {
                int n0 = nw * 64 + nt * 8 + rg;
                b[nt][0] = Wk0[n0];
                b[nt][1] = Wk1[n0];
            }
#pragma unroll
            for (int mt = 0; mt < 2; ++mt)
#pragma unroll
                for (int nt = 0; nt < 8; ++nt)
                    mma_f16(acc[mt][nt], a[mt], b[nt]);
        }
        __syncthreads();
    }

    // ---- epilogue: h = relu(acc + P_i + Q_j) -> hs (R13-exact) ----
#pragma unroll
    for (int mt = 0; mt < 2; ++mt) {
        int rA = mw * 32 + mt * 16 + rg;
        int rB = rA + 8;
        const float* qA = g_PQ + (size_t)(b64 + rA) * 512 + 256;
        const float* qB = g_PQ + (size_t)(b64 + rB) * 512 + 256;
#pragma unroll
        for (int nt = 0; nt < 8; ++nt) {
            int c0 = nw * 64 + nt * 8 + tg * 2;
            float2 pv = *(const float2*)(ps + c0);
            float2 qa = *(const float2*)(qA + c0);
            float2 qb = *(const float2*)(qB + c0);
            float h0 = fmaxf(acc[mt][nt][0] + pv.x + qa.x, 0.f);
            float h1 = fmaxf(acc[mt][nt][1] + pv.y + qa.y, 0.f);
            float h2 = fmaxf(acc[mt][nt][2] + pv.x + qb.x, 0.f);
            float h3 = fmaxf(acc[mt][nt][3] + pv.y + qb.y, 0.f);
            *(float2*)(hs + rA * 260 + c0) = make_float2(h0, h1);
            *(float2*)(hs + rB * 260 + c0) = make_float2(h2, h3);
        }
    }
    __syncthreads();

    // ---- h -> gmem ----
    float* hout = out + OUT_H_OFF + (size_t)bid * 64 * 256;
#pragma unroll
    for (int rr = wid * 8; rr < wid * 8 + 8; ++rr) {
#pragma unroll
        for (int q = 0; q < 2; ++q) {
            float4 v = *(const float4*)(hs + rr * 260 + q * 128 + l * 4);
            *(float4*)(hout + (size_t)rr * 256 + q * 128 + l * 4) = v;
        }
    }

    // ---- coef[j] = sum_d h[j][d] * wc[d] ----
    {
        int j = tid & 63, seg = tid >> 6;
        float s = 0.f;
#pragma unroll 8
        for (int d = 0; d < 64; ++d)
            s += hs[j * 260 + seg * 64 + d] * wcs[seg * 64 + d];
        cp[seg * 64 + j] = s;
    }
    __syncthreads();
    if (tid < 64)
        coef_s[tid] = cp[tid] + cp[64 + tid] + cp[128 + tid] + cp[192 + tid]
                    - ((tid == i_g) ? 1e9f : 0.f);
    __syncthreads();

    // ---- softmax ----
    float mval = -3.0e38f;
#pragma unroll 8
    for (int j = 0; j < 64; ++j) mval = fmaxf(mval, coef_s[j]);
    if (tid < 64) attn_s[tid] = __expf(coef_s[tid] - mval);
    __syncthreads();

    float ssum = 0.f;
#pragma unroll 8
    for (int j = 0; j < 64; ++j) ssum += attn_s[j];
    float inv = 1.f / ssum;

    // ---- residual ----
    float r = 0.f;
#pragma unroll 8
    for (int j = 0; j < 64; ++j)
        r += attn_s[j] * hs[j * 260 + tid];
    g_res[(size_t)bid * 256 + tid] = r * inv;
}

// ===========================================================================
// Kernel C: new_nodes = nodes + relu(g_res @ W_out + b_out). (unchanged)
// ===========================================================================
__global__ __launch_bounds__(256) void finalize3(
    const float* __restrict__ nodes, const float* __restrict__ W_out,
    const float* __restrict__ b_out, float* __restrict__ out)
{
    __shared__ float rs[8 * 256];
    __shared__ float red[8 * 128];
    const int tid = threadIdx.x;
    const int c0 = blockIdx.x * 128;
    const int r0 = blockIdx.y * 8;
    const int lc = tid & 127;
    const int c  = c0 + lc;
    const int kh = tid >> 7;

#pragma unroll
    for (int u = 0; u < 8; ++u)
        rs[u * 256 + tid] = g_res[(size_t)(r0 + u) * 256 + tid];
    __syncthreads();

    float acc[8];
#pragma unroll
    for (int q = 0; q < 8; ++q) acc[q] = 0.f;

    const int kbase = kh * 128;
    const float* Wp = W_out + (size_t)kbase * 256 + c;

#pragma unroll 8
    for (int k4 = 0; k4 < 32; ++k4) {
        float w0 = Wp[(size_t)(k4 * 4 + 0) * 256];
        float w1 = Wp[(size_t)(k4 * 4 + 1) * 256];
        float w2 = Wp[(size_t)(k4 * 4 + 2) * 256];
        float w3 = Wp[(size_t)(k4 * 4 + 3) * 256];
#pragma unroll
        for (int q = 0; q < 8; ++q) {
            float4 rv = *(const float4*)(rs + q * 256 + kbase + k4 * 4);
            acc[q] += rv.x * w0 + rv.y * w1 + rv.z * w2 + rv.w * w3;
        }
    }

    if (kh) {
#pragma unroll
        for (int q = 0; q < 8; ++q) red[q * 128 + lc] = acc[q];
    }
    __syncthreads();
    if (!kh) {
        float bo = b_out[c];
#pragma unroll
        for (int q = 0; q < 8; ++q) {
            float v = acc[q] + red[q * 128 + lc] + bo;
            out[(size_t)(r0 + q) * 256 + c] =
                nodes[(size_t)(r0 + q) * 256 + c] + fmaxf(v, 0.f);
        }
    }
}

// ===========================================================================
extern "C" void kernel_launch(void* const* d_in, const int* in_sizes, int n_in,
                              void* d_out, int out_size) {
    const float* nodes  = (const float*)d_in[0];
    const float* edges  = (const float*)d_in[1];
    const float* W_in   = (const float*)d_in[2];
    const float* b_in   = (const float*)d_in[3];
    const float* W_coef = (const float*)d_in[4];
    // d_in[5] = b_coef: softmax-invariant, skipped
    const float* W_out  = (const float*)d_in[6];
    const float* b_out  = (const float*)d_in[7];
    float* out = (float*)d_out;

    static int smem_set = 0;
    if (!smem_set) {
        cudaFuncSetAttribute(gnn_main10, cudaFuncAttributeMaxDynamicSharedMemorySize, SMEM_BYTES);
        smem_set = 1;
    }

    prep9<<<160, 256>>>(nodes, W_in, b_in);
    gnn_main10<<<1024, 256, SMEM_BYTES>>>(edges, W_coef, out);
    finalize3<<<dim3(2, 128), 256>>>(nodes, W_out, b_out, out);
}